// round 11
// baseline (speedup 1.0000x reference)
#include <cuda_runtime.h>

#define NPTS    25600
#define XROW    407
#define NSTEPS  50
#define DTF     0.001f
#define NBLK    148
#define TPB     352       // 11 warps; 88 quads; 87 active; each quad = 2 points
#define ACT_QUADS 87      // ceil(12800 point-pairs / 148)

typedef unsigned long long u64;

// ---------- packed f32x2 primitives ----------
__device__ __forceinline__ u64 pk(float lo, float hi) {
    u64 r; asm("mov.b64 %0, {%1,%2};" : "=l"(r) : "f"(lo), "f"(hi)); return r;
}
__device__ __forceinline__ void upk(u64 v, float& lo, float& hi) {
    asm("mov.b64 {%0,%1}, %2;" : "=f"(lo), "=f"(hi) : "l"(v));
}
__device__ __forceinline__ u64 ffma2(u64 a, u64 b, u64 c) {
    u64 d; asm("fma.rn.f32x2 %0, %1, %2, %3;" : "=l"(d) : "l"(a), "l"(b), "l"(c)); return d;
}
__device__ __forceinline__ u64 fmul2(u64 a, u64 b) {
    u64 d; asm("mul.rn.f32x2 %0, %1, %2;" : "=l"(d) : "l"(a), "l"(b)); return d;
}
__device__ __forceinline__ u64 fadd2(u64 a, u64 b) {
    u64 d; asm("add.rn.f32x2 %0, %1, %2;" : "=l"(d) : "l"(a), "l"(b)); return d;
}

__device__ __forceinline__ float softplus_f(float z) {
    float e = __expf(-fabsf(z));
    return fmaxf(z, 0.0f) + __logf(1.0f + e);
}
__device__ __forceinline__ float sig_only(float z) {
    float e = __expf(-fabsf(z));
    float u = 1.0f + e;
    float r; asm("rcp.approx.f32 %0, %1;" : "=f"(r) : "f"(u));
    return (z >= 0.0f) ? r : e * r;
}
__device__ __forceinline__ float sig_from_h(float h) { return 1.0f - __expf(-h); }

__device__ __forceinline__ u64 softplus2(u64 z) {
    float a, b; upk(z, a, b); return pk(softplus_f(a), softplus_f(b));
}
__device__ __forceinline__ u64 sig2(u64 z) {
    float a, b; upk(z, a, b); return pk(sig_only(a), sig_only(b));
}
__device__ __forceinline__ u64 sig2h(u64 h) {
    float a, b; upk(h, a, b); return pk(sig_from_h(a), sig_from_h(b));
}

// ---------- quad exchange: assemble full vector from own residue-q slices ----
// own[j] corresponds to index 4j+q.
__device__ __forceinline__ void quad_asm32(u64* v, const u64* own, int q) {
    u64 p[16];
    const bool lowq = (q & 1) == 0;
    #pragma unroll
    for (int j = 0; j < 8; ++j) {
        u64 t = __shfl_xor_sync(0xffffffffu, own[j], 1);
        p[2*j]     = lowq ? own[j] : t;
        p[2*j + 1] = lowq ? t : own[j];
    }
    const bool lo2 = (q & 2) == 0;
    #pragma unroll
    for (int k = 0; k < 16; ++k) {
        u64 u = __shfl_xor_sync(0xffffffffu, p[k], 2);
        int j = k >> 1, s = k & 1;
        v[4*j + (lo2 ? s     : 2 + s)] = p[k];
        v[4*j + (lo2 ? 2 + s : s    )] = u;
    }
}
__device__ __forceinline__ void quad_asm16(u64* v, const u64* own, int q) {
    u64 p[8];
    const bool lowq = (q & 1) == 0;
    #pragma unroll
    for (int j = 0; j < 4; ++j) {
        u64 t = __shfl_xor_sync(0xffffffffu, own[j], 1);
        p[2*j]     = lowq ? own[j] : t;
        p[2*j + 1] = lowq ? t : own[j];
    }
    const bool lo2 = (q & 2) == 0;
    #pragma unroll
    for (int k = 0; k < 8; ++k) {
        u64 u = __shfl_xor_sync(0xffffffffu, p[k], 2);
        int j = k >> 1, s = k & 1;
        v[4*j + (lo2 ? s     : 2 + s)] = p[k];
        v[4*j + (lo2 ? 2 + s : s    )] = u;
    }
}

// ---------- smem layout (floats); weights duplicated (w,w) for f32x2 --------
// forward: natural row order; lanes read 4 consecutive rows; strides 144/272B
// (= 16 mod 128) -> conflict-free.
#define OFW1  0                         // 32 * 36 = 1152
#define OFW2  (OFW1 + 1152)             // 32 * 68 = 2176
#define OFW3  (OFW2 + 2176)             // 16 * 68 = 1088
// backward: per-lane column slices (cols 4j+q); slice strides = 32 mod 128B.
#define OBW3  (OFW3 + 1088)             // 4 * 264  (16 rows * 16f + 8 pad)
#define OBW2  (OBW3 + 4*264)            // 4 * 520  (32 rows * 16f + 8 pad)
#define OBW1  (OBW2 + 4*520)            // 4 * 264  (32 rows * 8f  + 8 pad)
#define OPW0  (OBW1 + 4*264)            // 16 * 4
#define OPW4  (OPW0 + 64)               // 16 * 2
#define OPB0  (OPW4 + 32)
#define OPB1  (OPB0 + 32)               // 32 * 2
#define OPB2  (OPB1 + 64)
#define OPB3  (OPB2 + 64)               // 16 * 2
#define OSWT  (OPB3 + 32)
#define SMEMF (OSWT + 8)

__global__ void __launch_bounds__(TPB, 1)
phinn_kernel(const float* __restrict__ x,
             const float* __restrict__ w0, const float* __restrict__ b0,
             const float* __restrict__ w1, const float* __restrict__ b1,
             const float* __restrict__ w2, const float* __restrict__ b2,
             const float* __restrict__ w3, const float* __restrict__ b3,
             const float* __restrict__ w4,
             const float* __restrict__ wt,
             float* __restrict__ out)
{
    __shared__ __align__(16) float sm[SMEMF];
    const int tid = threadIdx.x;
    const int qid = tid >> 2;
    const int q   = tid & 3;

    // ---- stage packed weights ----
    for (int i = tid; i < 512; i += TPB) {         // w1 fwd
        int o = i >> 4, k = i & 15; float w = w1[i];
        int ix = OFW1 + o*36 + 2*k; sm[ix] = w; sm[ix+1] = w;
    }
    for (int i = tid; i < 1024; i += TPB) {        // w2 fwd
        int o = i >> 5, k = i & 31; float w = w2[i];
        int ix = OFW2 + o*68 + 2*k; sm[ix] = w; sm[ix+1] = w;
    }
    for (int i = tid; i < 512; i += TPB) {         // w3 fwd
        int o = i >> 5, k = i & 31; float w = w3[i];
        int ix = OFW3 + o*68 + 2*k; sm[ix] = w; sm[ix+1] = w;
    }
    for (int i = tid; i < 512; i += TPB) {         // w3 bwd slices [lq][o][j] = w3[o*32+4j+lq]
        int lq = i >> 7, o = (i >> 3) & 15, j = i & 7;
        float w = w3[o*32 + 4*j + lq];
        int ix = OBW3 + lq*264 + o*16 + 2*j; sm[ix] = w; sm[ix+1] = w;
    }
    for (int i = tid; i < 1024; i += TPB) {        // w2 bwd slices [lq][o][j] = w2[o*32+4j+lq]
        int lq = i >> 8, o = (i >> 3) & 31, j = i & 7;
        float w = w2[o*32 + 4*j + lq];
        int ix = OBW2 + lq*520 + o*16 + 2*j; sm[ix] = w; sm[ix+1] = w;
    }
    for (int i = tid; i < 512; i += TPB) {         // w1 bwd slices [lq][o][j] = w1[o*16+4j+lq]
        int lq = i >> 7, o = (i >> 2) & 31, j = i & 3;
        float w = w1[o*16 + 4*j + lq];
        int ix = OBW1 + lq*264 + o*8 + 2*j; sm[ix] = w; sm[ix+1] = w;
    }
    if (tid < 16) {
        int o = tid;
        sm[OPW0 + o*4 + 0] = w0[2*o];   sm[OPW0 + o*4 + 1] = w0[2*o];
        sm[OPW0 + o*4 + 2] = w0[2*o+1]; sm[OPW0 + o*4 + 3] = w0[2*o+1];
        sm[OPW4 + o*2] = w4[o]; sm[OPW4 + o*2 + 1] = w4[o];
        sm[OPB0 + o*2] = b0[o]; sm[OPB0 + o*2 + 1] = b0[o];
        sm[OPB3 + o*2] = b3[o]; sm[OPB3 + o*2 + 1] = b3[o];
    }
    if (tid < 32) {
        int o = tid;
        sm[OPB1 + o*2] = b1[o]; sm[OPB1 + o*2 + 1] = b1[o];
        sm[OPB2 + o*2] = b2[o]; sm[OPB2 + o*2 + 1] = b2[o];
    }
    if (tid < 4) sm[OSWT + tid] = wt[tid];
    __syncthreads();

    // ---- point-pair assignment ----
    const int  prIdx  = blockIdx.x * ACT_QUADS + qid;
    const bool active = (qid < ACT_QUADS) && (prIdx < NPTS / 2);
    const int  pr = active ? prIdx : (NPTS / 2 - 1);
    const int  pA = 2 * pr, pB = pA + 1;
    const int  bA = pA / 200, cA = pA - bA * 200;
    const int  bB = pB / 200, cB = pB - bB * 200;
    const float* xA = x + bA * XROW;
    const float* xB = x + bB * XROW;

    u64 y0p = pk(xA[2 + 2*cA], xB[2 + 2*cB]);
    u64 y1p = pk(xA[3 + 2*cA], xB[3 + 2*cB]);
    float tsA = xA[0], tsB = xB[0];
    const float spA = xA[402], spB = xB[402];
    const float wt0 = sm[OSWT], wt1 = sm[OSWT+1], wt2 = sm[OSWT+2], wt3 = sm[OSWT+3];
    const float tA0A = fmaf(xA[403], wt0, xA[404] * wt1);
    const float tA1A = fmaf(xA[403], wt2, xA[404] * wt3);
    const float tB0A = fmaf(xA[405], wt0, xA[406] * wt1);
    const float tB1A = fmaf(xA[405], wt2, xA[406] * wt3);
    const float tA0B = fmaf(xB[403], wt0, xB[404] * wt1);
    const float tA1B = fmaf(xB[403], wt2, xB[404] * wt3);
    const float tB0B = fmaf(xB[405], wt0, xB[406] * wt1);
    const float tB1B = fmaf(xB[405], wt2, xB[406] * wt3);
    const u64 NDT2 = pk(-DTF, -DTF);

    const float* __restrict__ smv = sm;

    #pragma unroll 1
    for (int it = 0; it < NSTEPS; ++it) {
        const bool eA = (tsA < spA), eB = (tsB < spB);
        const u64 ti0 = pk(eA ? tA0A : tB0A, eB ? tA0B : tB0B);
        const u64 ti1 = pk(eA ? tA1A : tB1A, eB ? tA1B : tB1B);

        // ---- L1: own 4 of 16 (o = 4j+q) ----
        u64 h1o[4];
        #pragma unroll
        for (int j = 0; j < 4; ++j) {
            int o = 4*j + q;
            u64 wa = *(const u64*)(smv + OPW0 + o*4);
            u64 wb = *(const u64*)(smv + OPW0 + o*4 + 2);
            u64 bb = *(const u64*)(smv + OPB0 + o*2);
            h1o[j] = softplus2(ffma2(wa, y0p, ffma2(wb, y1p, bb)));
        }
        u64 v16[16];
        quad_asm16(v16, h1o, q);

        // ---- L2: own 8 of 32 ----
        u64 h2o[8];
        #pragma unroll
        for (int j = 0; j < 8; ++j) {
            int o = 4*j + q;
            u64 z = *(const u64*)(smv + OPB1 + o*2);
            const ulonglong2* wr = (const ulonglong2*)(smv + OFW1 + o*36);
            #pragma unroll
            for (int t = 0; t < 8; ++t) {
                ulonglong2 w = wr[t];
                z = ffma2(w.x, v16[2*t], z);
                z = ffma2(w.y, v16[2*t + 1], z);
            }
            h2o[j] = softplus2(z);
        }
        u64 v32[32];
        quad_asm32(v32, h2o, q);

        // ---- L3: own 8 of 32 ----
        u64 h3o[8];
        #pragma unroll
        for (int j = 0; j < 8; ++j) {
            int o = 4*j + q;
            u64 z = *(const u64*)(smv + OPB2 + o*2);
            const ulonglong2* wr = (const ulonglong2*)(smv + OFW2 + o*68);
            #pragma unroll
            for (int t = 0; t < 16; ++t) {
                ulonglong2 w = wr[t];
                z = ffma2(w.x, v32[2*t], z);
                z = ffma2(w.y, v32[2*t + 1], z);
            }
            h3o[j] = softplus2(z);
        }
        quad_asm32(v32, h3o, q);

        // ---- L4: own 4 of 16; g4 = sigmoid(z4)*w4 ----
        u64 g4o[4];
        #pragma unroll
        for (int j = 0; j < 4; ++j) {
            int o = 4*j + q;
            u64 z = *(const u64*)(smv + OPB3 + o*2);
            const ulonglong2* wr = (const ulonglong2*)(smv + OFW3 + o*68);
            #pragma unroll
            for (int t = 0; t < 16; ++t) {
                ulonglong2 w = wr[t];
                z = ffma2(w.x, v32[2*t], z);
                z = ffma2(w.y, v32[2*t + 1], z);
            }
            g4o[j] = fmul2(sig2(z), *(const u64*)(smv + OPW4 + o*2));
        }
        u64 g16[16];
        quad_asm16(g16, g4o, q);

        // ---- g3: own cols (4j+q); a = w3^T g4 ----
        u64 a[8];
        #pragma unroll
        for (int j = 0; j < 8; ++j) a[j] = 0ULL;
        #pragma unroll
        for (int o = 0; o < 16; ++o) {
            const u64 go = g16[o];
            const ulonglong2* wr = (const ulonglong2*)(smv + OBW3 + q*264 + o*16);
            #pragma unroll
            for (int t = 0; t < 4; ++t) {
                ulonglong2 w = wr[t];
                a[2*t]     = ffma2(w.x, go, a[2*t]);
                a[2*t + 1] = ffma2(w.y, go, a[2*t + 1]);
            }
        }
        u64 g3o[8];
        #pragma unroll
        for (int j = 0; j < 8; ++j) g3o[j] = fmul2(a[j], sig2h(h3o[j]));
        quad_asm32(v32, g3o, q);

        // ---- g2: own cols; a = w2^T g3 ----
        #pragma unroll
        for (int j = 0; j < 8; ++j) a[j] = 0ULL;
        #pragma unroll
        for (int o = 0; o < 32; ++o) {
            const u64 go = v32[o];
            const ulonglong2* wr = (const ulonglong2*)(smv + OBW2 + q*520 + o*16);
            #pragma unroll
            for (int t = 0; t < 4; ++t) {
                ulonglong2 w = wr[t];
                a[2*t]     = ffma2(w.x, go, a[2*t]);
                a[2*t + 1] = ffma2(w.y, go, a[2*t + 1]);
            }
        }
        u64 g2o[8];
        #pragma unroll
        for (int j = 0; j < 8; ++j) g2o[j] = fmul2(a[j], sig2h(h2o[j]));
        quad_asm32(v32, g2o, q);

        // ---- g1: own cols (4 of 16); gy partials; quad reduce ----
        u64 a4[4];
        #pragma unroll
        for (int j = 0; j < 4; ++j) a4[j] = 0ULL;
        #pragma unroll
        for (int o = 0; o < 32; ++o) {
            const u64 go = v32[o];
            const ulonglong2* wr = (const ulonglong2*)(smv + OBW1 + q*264 + o*8);
            #pragma unroll
            for (int t = 0; t < 2; ++t) {
                ulonglong2 w = wr[t];
                a4[2*t]     = ffma2(w.x, go, a4[2*t]);
                a4[2*t + 1] = ffma2(w.y, go, a4[2*t + 1]);
            }
        }
        u64 gy0 = 0ULL, gy1 = 0ULL;
        #pragma unroll
        for (int j = 0; j < 4; ++j) {
            int o = 4*j + q;
            u64 g1 = fmul2(a4[j], sig2h(h1o[j]));
            gy0 = ffma2(*(const u64*)(smv + OPW0 + o*4),     g1, gy0);
            gy1 = ffma2(*(const u64*)(smv + OPW0 + o*4 + 2), g1, gy1);
        }
        gy0 = fadd2(gy0, __shfl_xor_sync(0xffffffffu, gy0, 1));
        gy0 = fadd2(gy0, __shfl_xor_sync(0xffffffffu, gy0, 2));
        gy1 = fadd2(gy1, __shfl_xor_sync(0xffffffffu, gy1, 1));
        gy1 = fadd2(gy1, __shfl_xor_sync(0xffffffffu, gy1, 2));

        y0p = ffma2(fadd2(gy0, ti0), NDT2, y0p);
        y1p = ffma2(fadd2(gy1, ti1), NDT2, y1p);
        tsA += DTF; tsB += DTF;
    }

    if (active && q == 0) {
        float a0, b0v, a1, b1v;
        upk(y0p, a0, b0v); upk(y1p, a1, b1v);
        out[2*pA]     = a0;  out[2*pA + 1] = a1;
        out[2*pB]     = b0v; out[2*pB + 1] = b1v;
    }
}

extern "C" void kernel_launch(void* const* d_in, const int* in_sizes, int n_in,
                              void* d_out, int out_size)
{
    int xi = -1;
    for (int i = 0; i < n_in; ++i)
        if (in_sizes[i] == 128 * XROW) { xi = i; break; }

    const float *x, *W[5], *B[5], *wtp;
    if (xi == 0) {
        x = (const float*)d_in[0];
        for (int i = 0; i < 5; ++i) {
            W[i] = (const float*)d_in[1 + 2 * i];
            B[i] = (const float*)d_in[2 + 2 * i];
        }
        wtp = (const float*)d_in[11];
    } else {
        for (int i = 0; i < 5; ++i) {
            W[i] = (const float*)d_in[2 * i];
            B[i] = (const float*)d_in[2 * i + 1];
        }
        wtp = (const float*)d_in[10];
        x   = (const float*)d_in[(xi >= 0) ? xi : 11];
    }

    float* out = (float*)d_out;
    phinn_kernel<<<NBLK, TPB>>>(x,
                                W[0], B[0], W[1], B[1], W[2], B[2],
                                W[3], B[3], W[4], wtp, out);
}

// round 12
// speedup vs baseline: 1.3758x; 1.3758x over previous
#include <cuda_runtime.h>

#define NPTS    25600
#define XROW    407
#define NSTEPS  50
#define DTF     0.001f
#define NBLK    148
#define TPB     352       // 11 warps; 176 pairs; 173 active; 1 point per pair
#define PAIRS_ACTIVE 173

typedef unsigned long long u64;

// ---------- packed f32x2 primitives ----------
__device__ __forceinline__ u64 pk(float lo, float hi) {
    u64 r; asm("mov.b64 %0, {%1,%2};" : "=l"(r) : "f"(lo), "f"(hi)); return r;
}
__device__ __forceinline__ void upk(u64 v, float& lo, float& hi) {
    asm("mov.b64 {%0,%1}, %2;" : "=f"(lo), "=f"(hi) : "l"(v));
}
__device__ __forceinline__ u64 ffma2(u64 a, u64 b, u64 c) {
    u64 d; asm("fma.rn.f32x2 %0, %1, %2, %3;" : "=l"(d) : "l"(a), "l"(b), "l"(c)); return d;
}
__device__ __forceinline__ u64 fmul2(u64 a, u64 b) {
    u64 d; asm("mul.rn.f32x2 %0, %1, %2;" : "=l"(d) : "l"(a), "l"(b)); return d;
}
__device__ __forceinline__ float softplus_f(float z) {
    float e = __expf(-fabsf(z));
    return fmaxf(z, 0.0f) + __logf(1.0f + e);
}
__device__ __forceinline__ float sig_only(float z) {
    float e = __expf(-fabsf(z));
    float u = 1.0f + e;
    float r; asm("rcp.approx.f32 %0, %1;" : "=f"(r) : "f"(u));
    return (z >= 0.0f) ? r : e * r;
}
__device__ __forceinline__ float sig_from_h(float h) { return 1.0f - __expf(-h); }

__device__ __forceinline__ u64 softplus2(u64 z) {
    float a, b; upk(z, a, b); return pk(softplus_f(a), softplus_f(b));
}
__device__ __forceinline__ u64 sig2(u64 z) {
    float a, b; upk(z, a, b); return pk(sig_only(a), sig_only(b));
}
__device__ __forceinline__ u64 sig2h(u64 h) {
    float a, b; upk(h, a, b); return pk(sig_from_h(a), sig_from_h(b));
}
// split pack (a,b) into dup packs (a,a),(b,b)
__device__ __forceinline__ void dup2(u64 p, u64& lo, u64& hi) {
    float a, b; upk(p, a, b); lo = pk(a, a); hi = pk(b, b);
}

// ---------- smem layout (float offsets) ----------
// forward neuron-pair packed, phys-row interleaved (2t+half), padded strides
#define OF1   0                 // 16 rows * 36  (w1: pack (w[2j][k],w[2j+1][k]))
#define OF2   (OF1 + 16*36)     // 16 rows * 68  (w2)
#define OF3   (OF2 + 16*68)     // 8  rows * 68  (w3)
// backward: plain row-major, padded strides (broadcast rows; halves 64/32B apart)
#define OB3   (OF3 + 8*68)      // 16 * 36
#define OB2   (OB3 + 16*36)     // 32 * 36
#define OB1   (OB2 + 32*36)     // 32 * 20
#define OW0P  (OB1 + 32*20)     // 8 rows * 4: (w0[2j][0],w0[2j+1][0],w0[2j][1],w0[2j+1][1])
#define OW4   (OW0P + 32)       // 16
#define OB0s  (OW4 + 16)        // 16
#define OB1s  (OB0s + 16)       // 32
#define OB2s  (OB1s + 32)       // 32
#define OB3s  (OB2s + 32)       // 16
#define OWT   (OB3s + 16)       // 4
#define SMEMF (OWT + 8)

__global__ void __launch_bounds__(TPB, 1)
phinn_kernel(const float* __restrict__ x,
             const float* __restrict__ w0, const float* __restrict__ b0,
             const float* __restrict__ w1, const float* __restrict__ b1,
             const float* __restrict__ w2, const float* __restrict__ b2,
             const float* __restrict__ w3, const float* __restrict__ b3,
             const float* __restrict__ w4,
             const float* __restrict__ wt,
             float* __restrict__ out)
{
    __shared__ __align__(16) float sm[SMEMF];
    const int tid  = threadIdx.x;
    const int pid  = tid >> 1;
    const int half = tid & 1;
    const bool hb  = (half != 0);

    // ---- stage weights ----
    for (int i = tid; i < 512; i += TPB) {          // w1 fwd packs
        int o = i >> 4, k = i & 15, j = o >> 1, par = o & 1;
        int pr = 2 * (j & 7) + (j >> 3);
        sm[OF1 + pr*36 + 2*k + par] = w1[i];
    }
    for (int i = tid; i < 1024; i += TPB) {         // w2 fwd packs
        int o = i >> 5, k = i & 31, j = o >> 1, par = o & 1;
        int pr = 2 * (j & 7) + (j >> 3);
        sm[OF2 + pr*68 + 2*k + par] = w2[i];
    }
    for (int i = tid; i < 512; i += TPB) {          // w3 fwd packs
        int o = i >> 5, k = i & 31, j = o >> 1, par = o & 1;
        int pr = 2 * (j & 3) + (j >> 2);
        sm[OF3 + pr*68 + 2*k + par] = w3[i];
    }
    for (int i = tid; i < 512; i += TPB) {          // w3 bwd plain
        int o = i >> 5, c = i & 31;
        sm[OB3 + o*36 + c] = w3[i];
    }
    for (int i = tid; i < 1024; i += TPB) {         // w2 bwd plain
        int o = i >> 5, c = i & 31;
        sm[OB2 + o*36 + c] = w2[i];
    }
    for (int i = tid; i < 512; i += TPB) {          // w1 bwd plain
        int o = i >> 4, c = i & 15;
        sm[OB1 + o*20 + c] = w1[i];
    }
    if (tid < 8) {                                  // w0 packs
        int j = tid;
        int pr = 2 * (j & 3) + (j >> 2);
        sm[OW0P + pr*4 + 0] = w0[(2*j)*2];
        sm[OW0P + pr*4 + 1] = w0[(2*j+1)*2];
        sm[OW0P + pr*4 + 2] = w0[(2*j)*2 + 1];
        sm[OW0P + pr*4 + 3] = w0[(2*j+1)*2 + 1];
    }
    if (tid < 16) { sm[OW4 + tid] = w4[tid]; sm[OB0s + tid] = b0[tid]; sm[OB3s + tid] = b3[tid]; }
    if (tid < 32) { sm[OB1s + tid] = b1[tid]; sm[OB2s + tid] = b2[tid]; }
    if (tid < 4)  sm[OWT + tid] = wt[tid];
    __syncthreads();

    const int  preal  = blockIdx.x * PAIRS_ACTIVE + pid;
    const bool active = (pid < PAIRS_ACTIVE) && (preal < NPTS);
    const int  p  = active ? preal : (NPTS - 1);
    const int  b  = p / 200;
    const int  c  = p - b * 200;
    const float* xb = x + b * XROW;

    float y0 = xb[2 + 2 * c];
    float y1 = xb[3 + 2 * c];
    float ts = xb[0];
    const float sp0 = xb[402];
    const float tA0 = fmaf(xb[403], sm[OWT+0], xb[404] * sm[OWT+1]);
    const float tA1 = fmaf(xb[403], sm[OWT+2], xb[404] * sm[OWT+3]);
    const float tB0 = fmaf(xb[405], sm[OWT+0], xb[406] * sm[OWT+1]);
    const float tB1 = fmaf(xb[405], sm[OWT+2], xb[406] * sm[OWT+3]);

    const float* __restrict__ smv = sm;

    #pragma unroll 1
    for (int it = 0; it < NSTEPS; ++it) {
        const bool  early = (ts < sp0);
        const float ti0 = early ? tA0 : tB0;
        const float ti1 = early ? tA1 : tB1;

        const u64 yd0 = pk(y0, y0), yd1 = pk(y1, y1);

        // ---- L1: own 4 neuron-pairs (neurons 8h+2t, 8h+2t+1) ----
        u64 h1p[4];
        #pragma unroll
        for (int t = 0; t < 4; ++t) {
            const float* rp = smv + OW0P + (2*t + half) * 4;
            u64 wa = *(const u64*)rp;
            u64 wb = *(const u64*)(rp + 2);
            u64 bb = *(const u64*)(smv + OB0s + 8*half + 2*t);
            h1p[t] = softplus2(ffma2(wa, yd0, ffma2(wb, yd1, bb)));
        }
        // exchange + dup -> vd16
        u64 vd16[16];
        #pragma unroll
        for (int t = 0; t < 4; ++t) {
            u64 oth = __shfl_xor_sync(0xffffffffu, h1p[t], 1);
            u64 lo, hi;
            dup2(h1p[t], lo, hi);
            vd16[8*half + 2*t] = lo; vd16[8*half + 2*t + 1] = hi;
            dup2(oth, lo, hi);
            vd16[8*(1-half) + 2*t] = lo; vd16[8*(1-half) + 2*t + 1] = hi;
        }

        // ---- L2: own 8 pairs (neurons 16h+2t, +1) ----
        u64 h2p[8];
        #pragma unroll
        for (int t = 0; t < 8; ++t) {
            u64 z = *(const u64*)(smv + OB1s + 16*half + 2*t);
            const ulonglong2* wr = (const ulonglong2*)(smv + OF1 + (2*t + half) * 36);
            #pragma unroll
            for (int k = 0; k < 8; ++k) {
                ulonglong2 w = wr[k];
                z = ffma2(w.x, vd16[2*k], z);
                z = ffma2(w.y, vd16[2*k + 1], z);
            }
            h2p[t] = softplus2(z);
        }
        u64 vd32[32];
        #pragma unroll
        for (int t = 0; t < 8; ++t) {
            u64 oth = __shfl_xor_sync(0xffffffffu, h2p[t], 1);
            u64 lo, hi;
            dup2(h2p[t], lo, hi);
            vd32[16*half + 2*t] = lo; vd32[16*half + 2*t + 1] = hi;
            dup2(oth, lo, hi);
            vd32[16*(1-half) + 2*t] = lo; vd32[16*(1-half) + 2*t + 1] = hi;
        }

        // ---- L3: own 8 pairs ----
        u64 h3p[8];
        #pragma unroll
        for (int t = 0; t < 8; ++t) {
            u64 z = *(const u64*)(smv + OB2s + 16*half + 2*t);
            const ulonglong2* wr = (const ulonglong2*)(smv + OF2 + (2*t + half) * 68);
            #pragma unroll
            for (int k = 0; k < 16; ++k) {
                ulonglong2 w = wr[k];
                z = ffma2(w.x, vd32[2*k], z);
                z = ffma2(w.y, vd32[2*k + 1], z);
            }
            h3p[t] = softplus2(z);
        }
        #pragma unroll
        for (int t = 0; t < 8; ++t) {
            u64 oth = __shfl_xor_sync(0xffffffffu, h3p[t], 1);
            u64 lo, hi;
            dup2(h3p[t], lo, hi);
            vd32[16*half + 2*t] = lo; vd32[16*half + 2*t + 1] = hi;
            dup2(oth, lo, hi);
            vd32[16*(1-half) + 2*t] = lo; vd32[16*(1-half) + 2*t + 1] = hi;
        }

        // ---- L4: own 4 pairs (neurons 8h+2t,+1); g4 = sig(z)*w4 ----
        u64 g4p[4];
        #pragma unroll
        for (int t = 0; t < 4; ++t) {
            u64 z = *(const u64*)(smv + OB3s + 8*half + 2*t);
            const ulonglong2* wr = (const ulonglong2*)(smv + OF3 + (2*t + half) * 68);
            #pragma unroll
            for (int k = 0; k < 16; ++k) {
                ulonglong2 w = wr[k];
                z = ffma2(w.x, vd32[2*k], z);
                z = ffma2(w.y, vd32[2*k + 1], z);
            }
            g4p[t] = fmul2(sig2(z), *(const u64*)(smv + OW4 + 8*half + 2*t));
        }
        u64 gd16[16];
        #pragma unroll
        for (int t = 0; t < 4; ++t) {
            u64 oth = __shfl_xor_sync(0xffffffffu, g4p[t], 1);
            u64 lo, hi;
            dup2(g4p[t], lo, hi);
            gd16[8*half + 2*t] = lo; gd16[8*half + 2*t + 1] = hi;
            dup2(oth, lo, hi);
            gd16[8*(1-half) + 2*t] = lo; gd16[8*(1-half) + 2*t + 1] = hi;
        }

        // ---- g3: own col-pairs (16h+2t,+1); a = w3^T g4 ----
        u64 a[8];
        #pragma unroll
        for (int t = 0; t < 8; ++t) a[t] = 0ULL;
        #pragma unroll
        for (int o = 0; o < 16; ++o) {
            const u64 go = gd16[o];
            const ulonglong2* wr = (const ulonglong2*)(smv + OB3 + o*36 + 16*half);
            #pragma unroll
            for (int t = 0; t < 4; ++t) {
                ulonglong2 w = wr[t];
                a[2*t]     = ffma2(w.x, go, a[2*t]);
                a[2*t + 1] = ffma2(w.y, go, a[2*t + 1]);
            }
        }
        #pragma unroll
        for (int t = 0; t < 8; ++t) {
            u64 g3 = fmul2(a[t], sig2h(h3p[t]));
            u64 oth = __shfl_xor_sync(0xffffffffu, g3, 1);
            u64 lo, hi;
            dup2(g3, lo, hi);
            vd32[16*half + 2*t] = lo; vd32[16*half + 2*t + 1] = hi;
            dup2(oth, lo, hi);
            vd32[16*(1-half) + 2*t] = lo; vd32[16*(1-half) + 2*t + 1] = hi;
        }

        // ---- g2: own col-pairs; a = w2^T g3 ----
        #pragma unroll
        for (int t = 0; t < 8; ++t) a[t] = 0ULL;
        #pragma unroll
        for (int o = 0; o < 32; ++o) {
            const u64 go = vd32[o];
            const ulonglong2* wr = (const ulonglong2*)(smv + OB2 + o*36 + 16*half);
            #pragma unroll
            for (int t = 0; t < 4; ++t) {
                ulonglong2 w = wr[t];
                a[2*t]     = ffma2(w.x, go, a[2*t]);
                a[2*t + 1] = ffma2(w.y, go, a[2*t + 1]);
            }
        }
        #pragma unroll
        for (int t = 0; t < 8; ++t) {
            u64 g2 = fmul2(a[t], sig2h(h2p[t]));
            u64 oth = __shfl_xor_sync(0xffffffffu, g2, 1);
            u64 lo, hi;
            dup2(g2, lo, hi);
            vd32[16*half + 2*t] = lo; vd32[16*half + 2*t + 1] = hi;
            dup2(oth, lo, hi);
            vd32[16*(1-half) + 2*t] = lo; vd32[16*(1-half) + 2*t + 1] = hi;
        }

        // ---- g1: own col-pairs (8h+2t,+1); gy ----
        u64 a4[4];
        #pragma unroll
        for (int t = 0; t < 4; ++t) a4[t] = 0ULL;
        #pragma unroll
        for (int o = 0; o < 32; ++o) {
            const u64 go = vd32[o];
            const ulonglong2* wr = (const ulonglong2*)(smv + OB1 + o*20 + 8*half);
            #pragma unroll
            for (int t = 0; t < 2; ++t) {
                ulonglong2 w = wr[t];
                a4[2*t]     = ffma2(w.x, go, a4[2*t]);
                a4[2*t + 1] = ffma2(w.y, go, a4[2*t + 1]);
            }
        }
        u64 gy0p = 0ULL, gy1p = 0ULL;
        #pragma unroll
        for (int t = 0; t < 4; ++t) {
            u64 g1 = fmul2(a4[t], sig2h(h1p[t]));
            const float* rp = smv + OW0P + (2*t + half) * 4;
            gy0p = ffma2(*(const u64*)rp,       g1, gy0p);
            gy1p = ffma2(*(const u64*)(rp + 2), g1, gy1p);
        }
        float u, v;
        upk(gy0p, u, v); float gy0 = u + v;
        upk(gy1p, u, v); float gy1 = u + v;
        gy0 += __shfl_xor_sync(0xffffffffu, gy0, 1);
        gy1 += __shfl_xor_sync(0xffffffffu, gy1, 1);

        y0 = fmaf(-(gy0 + ti0), DTF, y0);
        y1 = fmaf(-(gy1 + ti1), DTF, y1);
        ts += DTF;
    }

    if (active) out[2 * p + half] = hb ? y1 : y0;
}

extern "C" void kernel_launch(void* const* d_in, const int* in_sizes, int n_in,
                              void* d_out, int out_size)
{
    int xi = -1;
    for (int i = 0; i < n_in; ++i)
        if (in_sizes[i] == 128 * XROW) { xi = i; break; }

    const float *x, *W[5], *B[5], *wtp;
    if (xi == 0) {
        x = (const float*)d_in[0];
        for (int i = 0; i < 5; ++i) {
            W[i] = (const float*)d_in[1 + 2 * i];
            B[i] = (const float*)d_in[2 + 2 * i];
        }
        wtp = (const float*)d_in[11];
    } else {
        for (int i = 0; i < 5; ++i) {
            W[i] = (const float*)d_in[2 * i];
            B[i] = (const float*)d_in[2 * i + 1];
        }
        wtp = (const float*)d_in[10];
        x   = (const float*)d_in[(xi >= 0) ? xi : 11];
    }

    float* out = (float*)d_out;
    phinn_kernel<<<NBLK, TPB>>>(x,
                                W[0], B[0], W[1], B[1], W[2], B[2],
                                W[3], B[3], W[4], wtp, out);
}

// round 13
// speedup vs baseline: 2.8467x; 2.0691x over previous
#include <cuda_runtime.h>

#define NPTS    25600
#define XROW    407
#define NSTEPS  50
#define DTF     0.001f
#define NBLK    148
#define TPB     352       // 11 warps; 176 pairs; 173 active; 1 point per pair
#define PAIRS_ACTIVE 173

typedef unsigned long long u64;

// ---------- packed f32x2 primitives ----------
__device__ __forceinline__ u64 pk(float lo, float hi) {
    u64 r; asm("mov.b64 %0, {%1,%2};" : "=l"(r) : "f"(lo), "f"(hi)); return r;
}
__device__ __forceinline__ void upk(u64 v, float& lo, float& hi) {
    asm("mov.b64 {%0,%1}, %2;" : "=f"(lo), "=f"(hi) : "l"(v));
}
__device__ __forceinline__ u64 ffma2(u64 a, u64 b, u64 c) {
    u64 d; asm("fma.rn.f32x2 %0, %1, %2, %3;" : "=l"(d) : "l"(a), "l"(b), "l"(c)); return d;
}
__device__ __forceinline__ u64 fmul2(u64 a, u64 b) {
    u64 d; asm("mul.rn.f32x2 %0, %1, %2;" : "=l"(d) : "l"(a), "l"(b)); return d;
}
__device__ __forceinline__ float softplus_f(float z) {
    float e = __expf(-fabsf(z));
    return fmaxf(z, 0.0f) + __logf(1.0f + e);
}
__device__ __forceinline__ float sig_only(float z) {
    float e = __expf(-fabsf(z));
    float u = 1.0f + e;
    float r; asm("rcp.approx.f32 %0, %1;" : "=f"(r) : "f"(u));
    return (z >= 0.0f) ? r : e * r;
}
__device__ __forceinline__ float sig_from_h(float h) { return 1.0f - __expf(-h); }

__device__ __forceinline__ u64 softplus2(u64 z) {
    float a, b; upk(z, a, b); return pk(softplus_f(a), softplus_f(b));
}
__device__ __forceinline__ u64 sig2(u64 z) {
    float a, b; upk(z, a, b); return pk(sig_only(a), sig_only(b));
}
__device__ __forceinline__ u64 sig2h(u64 h) {
    float a, b; upk(h, a, b); return pk(sig_from_h(a), sig_from_h(b));
}
// split pack (a,b) into dup packs (a,a),(b,b)
__device__ __forceinline__ void dup2(u64 p, u64& lo, u64& hi) {
    float a, b; upk(p, a, b); lo = pk(a, a); hi = pk(b, b);
}

// ---------- smem layout (float offsets) ----------
// forward neuron-pair packed, phys-row interleaved (2t+half), padded strides
#define OF1   0                 // 16 rows * 36  (w1: pack (w[2j][k],w[2j+1][k]))
#define OF2   (OF1 + 16*36)     // 16 rows * 68  (w2)
#define OF3   (OF2 + 16*68)     // 8  rows * 68  (w3)
// backward: plain row-major, padded strides (broadcast rows; halves 64/32B apart)
#define OB3   (OF3 + 8*68)      // 16 * 36
#define OB2   (OB3 + 16*36)     // 32 * 36
#define OB1   (OB2 + 32*36)     // 32 * 20
#define OW0P  (OB1 + 32*20)     // 8 rows * 4
#define OW4   (OW0P + 32)       // 16
#define OB0s  (OW4 + 16)        // 16
#define OB1s  (OB0s + 16)       // 32
#define OB2s  (OB1s + 32)       // 32
#define OB3s  (OB2s + 32)       // 16
#define OWT   (OB3s + 16)       // 4
#define SMEMF (OWT + 8)

__global__ void __launch_bounds__(TPB, 1)
phinn_kernel(const float* __restrict__ x,
             const float* __restrict__ w0, const float* __restrict__ b0,
             const float* __restrict__ w1, const float* __restrict__ b1,
             const float* __restrict__ w2, const float* __restrict__ b2,
             const float* __restrict__ w3, const float* __restrict__ b3,
             const float* __restrict__ w4,
             const float* __restrict__ wt,
             float* __restrict__ out)
{
    __shared__ __align__(16) float sm[SMEMF];
    const int tid  = threadIdx.x;
    const int pid  = tid >> 1;
    const int half = tid & 1;
    const bool hb  = (half != 0);

    // ---- stage weights ----
    for (int i = tid; i < 512; i += TPB) {          // w1 fwd packs
        int o = i >> 4, k = i & 15, j = o >> 1, par = o & 1;
        int pr = 2 * (j & 7) + (j >> 3);
        sm[OF1 + pr*36 + 2*k + par] = w1[i];
    }
    for (int i = tid; i < 1024; i += TPB) {         // w2 fwd packs
        int o = i >> 5, k = i & 31, j = o >> 1, par = o & 1;
        int pr = 2 * (j & 7) + (j >> 3);
        sm[OF2 + pr*68 + 2*k + par] = w2[i];
    }
    for (int i = tid; i < 512; i += TPB) {          // w3 fwd packs
        int o = i >> 5, k = i & 31, j = o >> 1, par = o & 1;
        int pr = 2 * (j & 3) + (j >> 2);
        sm[OF3 + pr*68 + 2*k + par] = w3[i];
    }
    for (int i = tid; i < 512; i += TPB) {          // w3 bwd plain
        int o = i >> 5, c = i & 31;
        sm[OB3 + o*36 + c] = w3[i];
    }
    for (int i = tid; i < 1024; i += TPB) {         // w2 bwd plain
        int o = i >> 5, c = i & 31;
        sm[OB2 + o*36 + c] = w2[i];
    }
    for (int i = tid; i < 512; i += TPB) {          // w1 bwd plain
        int o = i >> 4, c = i & 15;
        sm[OB1 + o*20 + c] = w1[i];
    }
    if (tid < 8) {                                  // w0 packs
        int j = tid;
        int pr = 2 * (j & 3) + (j >> 2);
        sm[OW0P + pr*4 + 0] = w0[(2*j)*2];
        sm[OW0P + pr*4 + 1] = w0[(2*j+1)*2];
        sm[OW0P + pr*4 + 2] = w0[(2*j)*2 + 1];
        sm[OW0P + pr*4 + 3] = w0[(2*j+1)*2 + 1];
    }
    if (tid < 16) { sm[OW4 + tid] = w4[tid]; sm[OB0s + tid] = b0[tid]; sm[OB3s + tid] = b3[tid]; }
    if (tid < 32) { sm[OB1s + tid] = b1[tid]; sm[OB2s + tid] = b2[tid]; }
    if (tid < 4)  sm[OWT + tid] = wt[tid];
    __syncthreads();

    const int  preal  = blockIdx.x * PAIRS_ACTIVE + pid;
    const bool active = (pid < PAIRS_ACTIVE) && (preal < NPTS);
    const int  p  = active ? preal : (NPTS - 1);
    const int  b  = p / 200;
    const int  c  = p - b * 200;
    const float* xb = x + b * XROW;

    float y0 = xb[2 + 2 * c];
    float y1 = xb[3 + 2 * c];
    float ts = xb[0];
    const float sp0 = xb[402];
    const float tA0 = fmaf(xb[403], sm[OWT+0], xb[404] * sm[OWT+1]);
    const float tA1 = fmaf(xb[403], sm[OWT+2], xb[404] * sm[OWT+3]);
    const float tB0 = fmaf(xb[405], sm[OWT+0], xb[406] * sm[OWT+1]);
    const float tB1 = fmaf(xb[405], sm[OWT+2], xb[406] * sm[OWT+3]);

    const float* __restrict__ smv = sm;

    // exchange macro: writes dup packs of (own,other) into arr at constant
    // indices [lo0+2t, lo0+2t+1] (half-0 block) / [hi0+2t, hi0+2t+1] (half-1 block)
    #define XCHG(arr, lo0, hi0, t, val)                                        \
        do {                                                                   \
            u64 _oth = __shfl_xor_sync(0xffffffffu, (val), 1);                 \
            u64 _lo_o, _hi_o, _lo_t, _hi_t;                                    \
            dup2((val), _lo_o, _hi_o);                                         \
            dup2(_oth, _lo_t, _hi_t);                                          \
            (arr)[(lo0) + 2*(t)]     = hb ? _lo_t : _lo_o;                     \
            (arr)[(lo0) + 2*(t) + 1] = hb ? _hi_t : _hi_o;                     \
            (arr)[(hi0) + 2*(t)]     = hb ? _lo_o : _lo_t;                     \
            (arr)[(hi0) + 2*(t) + 1] = hb ? _hi_o : _hi_t;                     \
        } while (0)

    #pragma unroll 1
    for (int it = 0; it < NSTEPS; ++it) {
        const bool  early = (ts < sp0);
        const float ti0 = early ? tA0 : tB0;
        const float ti1 = early ? tA1 : tB1;

        const u64 yd0 = pk(y0, y0), yd1 = pk(y1, y1);

        // ---- L1: own 4 neuron-pairs (neurons 8h+2t, 8h+2t+1) ----
        u64 h1p[4];
        #pragma unroll
        for (int t = 0; t < 4; ++t) {
            const float* rp = smv + OW0P + (2*t + half) * 4;
            u64 wa = *(const u64*)rp;
            u64 wb = *(const u64*)(rp + 2);
            u64 bb = *(const u64*)(smv + OB0s + 8*half + 2*t);
            h1p[t] = softplus2(ffma2(wa, yd0, ffma2(wb, yd1, bb)));
        }
        u64 vd16[16];
        #pragma unroll
        for (int t = 0; t < 4; ++t) XCHG(vd16, 0, 8, t, h1p[t]);

        // ---- L2: own 8 pairs (neurons 16h+2t, +1) ----
        u64 h2p[8];
        #pragma unroll
        for (int t = 0; t < 8; ++t) {
            u64 z = *(const u64*)(smv + OB1s + 16*half + 2*t);
            const ulonglong2* wr = (const ulonglong2*)(smv + OF1 + (2*t + half) * 36);
            #pragma unroll
            for (int k = 0; k < 8; ++k) {
                ulonglong2 w = wr[k];
                z = ffma2(w.x, vd16[2*k], z);
                z = ffma2(w.y, vd16[2*k + 1], z);
            }
            h2p[t] = softplus2(z);
        }
        u64 vd32[32];
        #pragma unroll
        for (int t = 0; t < 8; ++t) XCHG(vd32, 0, 16, t, h2p[t]);

        // ---- L3: own 8 pairs ----
        u64 h3p[8];
        #pragma unroll
        for (int t = 0; t < 8; ++t) {
            u64 z = *(const u64*)(smv + OB2s + 16*half + 2*t);
            const ulonglong2* wr = (const ulonglong2*)(smv + OF2 + (2*t + half) * 68);
            #pragma unroll
            for (int k = 0; k < 16; ++k) {
                ulonglong2 w = wr[k];
                z = ffma2(w.x, vd32[2*k], z);
                z = ffma2(w.y, vd32[2*k + 1], z);
            }
            h3p[t] = softplus2(z);
        }
        #pragma unroll
        for (int t = 0; t < 8; ++t) XCHG(vd32, 0, 16, t, h3p[t]);

        // ---- L4: own 4 pairs (neurons 8h+2t,+1); g4 = sig(z)*w4 ----
        u64 g4p[4];
        #pragma unroll
        for (int t = 0; t < 4; ++t) {
            u64 z = *(const u64*)(smv + OB3s + 8*half + 2*t);
            const ulonglong2* wr = (const ulonglong2*)(smv + OF3 + (2*t + half) * 68);
            #pragma unroll
            for (int k = 0; k < 16; ++k) {
                ulonglong2 w = wr[k];
                z = ffma2(w.x, vd32[2*k], z);
                z = ffma2(w.y, vd32[2*k + 1], z);
            }
            g4p[t] = fmul2(sig2(z), *(const u64*)(smv + OW4 + 8*half + 2*t));
        }
        u64 gd16[16];
        #pragma unroll
        for (int t = 0; t < 4; ++t) XCHG(gd16, 0, 8, t, g4p[t]);

        // ---- g3: own col-pairs (16h+2t,+1); a = w3^T g4 ----
        u64 a[8];
        #pragma unroll
        for (int t = 0; t < 8; ++t) a[t] = 0ULL;
        #pragma unroll
        for (int o = 0; o < 16; ++o) {
            const u64 go = gd16[o];
            const ulonglong2* wr = (const ulonglong2*)(smv + OB3 + o*36 + 16*half);
            #pragma unroll
            for (int t = 0; t < 4; ++t) {
                ulonglong2 w = wr[t];
                a[2*t]     = ffma2(w.x, go, a[2*t]);
                a[2*t + 1] = ffma2(w.y, go, a[2*t + 1]);
            }
        }
        #pragma unroll
        for (int t = 0; t < 8; ++t) {
            u64 g3 = fmul2(a[t], sig2h(h3p[t]));
            XCHG(vd32, 0, 16, t, g3);
        }

        // ---- g2: own col-pairs; a = w2^T g3 ----
        #pragma unroll
        for (int t = 0; t < 8; ++t) a[t] = 0ULL;
        #pragma unroll
        for (int o = 0; o < 32; ++o) {
            const u64 go = vd32[o];
            const ulonglong2* wr = (const ulonglong2*)(smv + OB2 + o*36 + 16*half);
            #pragma unroll
            for (int t = 0; t < 4; ++t) {
                ulonglong2 w = wr[t];
                a[2*t]     = ffma2(w.x, go, a[2*t]);
                a[2*t + 1] = ffma2(w.y, go, a[2*t + 1]);
            }
        }
        #pragma unroll
        for (int t = 0; t < 8; ++t) {
            u64 g2 = fmul2(a[t], sig2h(h2p[t]));
            XCHG(vd32, 0, 16, t, g2);
        }

        // ---- g1: own col-pairs (8h+2t,+1); gy ----
        u64 a4[4];
        #pragma unroll
        for (int t = 0; t < 4; ++t) a4[t] = 0ULL;
        #pragma unroll
        for (int o = 0; o < 32; ++o) {
            const u64 go = vd32[o];
            const ulonglong2* wr = (const ulonglong2*)(smv + OB1 + o*20 + 8*half);
            #pragma unroll
            for (int t = 0; t < 2; ++t) {
                ulonglong2 w = wr[t];
                a4[2*t]     = ffma2(w.x, go, a4[2*t]);
                a4[2*t + 1] = ffma2(w.y, go, a4[2*t + 1]);
            }
        }
        u64 gy0p = 0ULL, gy1p = 0ULL;
        #pragma unroll
        for (int t = 0; t < 4; ++t) {
            u64 g1 = fmul2(a4[t], sig2h(h1p[t]));
            const float* rp = smv + OW0P + (2*t + half) * 4;
            gy0p = ffma2(*(const u64*)rp,       g1, gy0p);
            gy1p = ffma2(*(const u64*)(rp + 2), g1, gy1p);
        }
        float u, v;
        upk(gy0p, u, v); float gy0 = u + v;
        upk(gy1p, u, v); float gy1 = u + v;
        gy0 += __shfl_xor_sync(0xffffffffu, gy0, 1);
        gy1 += __shfl_xor_sync(0xffffffffu, gy1, 1);

        y0 = fmaf(-(gy0 + ti0), DTF, y0);
        y1 = fmaf(-(gy1 + ti1), DTF, y1);
        ts += DTF;
    }

    if (active) out[2 * p + half] = hb ? y1 : y0;
}

extern "C" void kernel_launch(void* const* d_in, const int* in_sizes, int n_in,
                              void* d_out, int out_size)
{
    int xi = -1;
    for (int i = 0; i < n_in; ++i)
        if (in_sizes[i] == 128 * XROW) { xi = i; break; }

    const float *x, *W[5], *B[5], *wtp;
    if (xi == 0) {
        x = (const float*)d_in[0];
        for (int i = 0; i < 5; ++i) {
            W[i] = (const float*)d_in[1 + 2 * i];
            B[i] = (const float*)d_in[2 + 2 * i];
        }
        wtp = (const float*)d_in[11];
    } else {
        for (int i = 0; i < 5; ++i) {
            W[i] = (const float*)d_in[2 * i];
            B[i] = (const float*)d_in[2 * i + 1];
        }
        wtp = (const float*)d_in[10];
        x   = (const float*)d_in[(xi >= 0) ? xi : 11];
    }

    float* out = (float*)d_out;
    phinn_kernel<<<NBLK, TPB>>>(x,
                                W[0], B[0], W[1], B[1], W[2], B[2],
                                W[3], B[3], W[4], wtp, out);
}

// round 14
// speedup vs baseline: 2.8780x; 1.0110x over previous
#include <cuda_runtime.h>

#define NPTS    25600
#define XROW    407
#define NSTEPS  50
#define DTF     0.001f
#define NBLK    148
#define TPB     352       // 11 warps; 176 pairs; 173 active; 1 point per pair
#define PAIRS_ACTIVE 173

typedef unsigned long long u64;

// ---------- packed f32x2 primitives ----------
__device__ __forceinline__ u64 pk(float lo, float hi) {
    u64 r; asm("mov.b64 %0, {%1,%2};" : "=l"(r) : "f"(lo), "f"(hi)); return r;
}
__device__ __forceinline__ void upk(u64 v, float& lo, float& hi) {
    asm("mov.b64 {%0,%1}, %2;" : "=f"(lo), "=f"(hi) : "l"(v));
}
__device__ __forceinline__ u64 ffma2(u64 a, u64 b, u64 c) {
    u64 d; asm("fma.rn.f32x2 %0, %1, %2, %3;" : "=l"(d) : "l"(a), "l"(b), "l"(c)); return d;
}
__device__ __forceinline__ u64 fmul2(u64 a, u64 b) {
    u64 d; asm("mul.rn.f32x2 %0, %1, %2;" : "=l"(d) : "l"(a), "l"(b)); return d;
}
__device__ __forceinline__ float softplus_f(float z) {
    float e = __expf(-fabsf(z));
    return fmaxf(z, 0.0f) + __logf(1.0f + e);
}
__device__ __forceinline__ float sig_only(float z) {
    float e = __expf(-fabsf(z));
    float u = 1.0f + e;
    float r; asm("rcp.approx.f32 %0, %1;" : "=f"(r) : "f"(u));
    return (z >= 0.0f) ? r : e * r;
}
__device__ __forceinline__ float sig_from_h(float h) { return 1.0f - __expf(-h); }

__device__ __forceinline__ u64 softplus2(u64 z) {
    float a, b; upk(z, a, b); return pk(softplus_f(a), softplus_f(b));
}
__device__ __forceinline__ u64 sig2(u64 z) {
    float a, b; upk(z, a, b); return pk(sig_only(a), sig_only(b));
}
__device__ __forceinline__ u64 sig2h(u64 h) {
    float a, b; upk(h, a, b); return pk(sig_from_h(a), sig_from_h(b));
}
__device__ __forceinline__ void dup2(u64 p, u64& lo, u64& hi) {
    float a, b; upk(p, a, b); lo = pk(a, a); hi = pk(b, b);
}

// ---------- smem layout (float offsets); all regions 128B-aligned ----------
// forward: pack-row pairs (2t,2t+1) 16B-interleaved: half h, chunk c at
//   pairbase + c*32B + h*16B  -> both halves always in the same 128B line.
#define OF1   0       // L2 fwd: 8 pairs * 64  = 512
#define OF2   512     // L3 fwd: 8 pairs * 128 = 1024
#define OF3   1536    // L4 fwd: 4 pairs * 128 = 512
// backward: plain row-major, stride 32/16 floats, 128B-aligned bases;
//   halves' slices (+0/+64B) share the row's line.
#define OB3   2048    // 16 * 32 = 512
#define OB2   2560    // 32 * 32 = 1024
#define OB1   3584    // 32 * 16 = 512
#define OW0P  4096    // 8 pack-rows interleaved: pair t at +t*8, half at +h*4
#define OW4   4128
#define OB0s  4144
#define OB1s  4160
#define OB2s  4192
#define OB3s  4224
#define OWT   4240
#define SMEMF 4248

__global__ void __launch_bounds__(TPB, 1)
phinn_kernel(const float* __restrict__ x,
             const float* __restrict__ w0, const float* __restrict__ b0,
             const float* __restrict__ w1, const float* __restrict__ b1,
             const float* __restrict__ w2, const float* __restrict__ b2,
             const float* __restrict__ w3, const float* __restrict__ b3,
             const float* __restrict__ w4,
             const float* __restrict__ wt,
             float* __restrict__ out)
{
    __shared__ __align__(128) float sm[SMEMF];
    const int tid  = threadIdx.x;
    const int pid  = tid >> 1;
    const int half = tid & 1;
    const bool hb  = (half != 0);

    // ---- stage weights ----
    // fwd packs: pack-row j covers neurons (2j, 2j+1); float (row j, k, par)
    // stored at base + (j>>1)*PAIRSTRIDE + (k>>1)*8 + (j&1)*4 + (k&1)*2 + par
    for (int i = tid; i < 512; i += TPB) {          // w1 fwd (16 pack-rows, 16 ks)
        int o = i >> 4, k = i & 15, j = o >> 1, par = o & 1;
        sm[OF1 + (j >> 1)*64 + (k >> 1)*8 + (j & 1)*4 + (k & 1)*2 + par] = w1[i];
    }
    for (int i = tid; i < 1024; i += TPB) {         // w2 fwd (16 pack-rows, 32 ks)
        int o = i >> 5, k = i & 31, j = o >> 1, par = o & 1;
        sm[OF2 + (j >> 1)*128 + (k >> 1)*8 + (j & 1)*4 + (k & 1)*2 + par] = w2[i];
    }
    for (int i = tid; i < 512; i += TPB) {          // w3 fwd (8 pack-rows, 32 ks)
        int o = i >> 5, k = i & 31, j = o >> 1, par = o & 1;
        sm[OF3 + (j >> 1)*128 + (k >> 1)*8 + (j & 1)*4 + (k & 1)*2 + par] = w3[i];
    }
    for (int i = tid; i < 512; i += TPB) {          // w3 bwd plain (stride 32)
        int o = i >> 5, c = i & 31;
        sm[OB3 + o*32 + c] = w3[i];
    }
    for (int i = tid; i < 1024; i += TPB) {         // w2 bwd plain (stride 32)
        int o = i >> 5, c = i & 31;
        sm[OB2 + o*32 + c] = w2[i];
    }
    for (int i = tid; i < 512; i += TPB) {          // w1 bwd plain (stride 16)
        int o = i >> 4, c = i & 15;
        sm[OB1 + o*16 + c] = w1[i];
    }
    if (tid < 8) {                                  // w0 packs, pair-interleaved
        int j = tid;
        int base = OW0P + (j >> 1)*8 + (j & 1)*4;
        sm[base + 0] = w0[(2*j)*2];
        sm[base + 1] = w0[(2*j+1)*2];
        sm[base + 2] = w0[(2*j)*2 + 1];
        sm[base + 3] = w0[(2*j+1)*2 + 1];
    }
    if (tid < 16) { sm[OW4 + tid] = w4[tid]; sm[OB0s + tid] = b0[tid]; sm[OB3s + tid] = b3[tid]; }
    if (tid < 32) { sm[OB1s + tid] = b1[tid]; sm[OB2s + tid] = b2[tid]; }
    if (tid < 4)  sm[OWT + tid] = wt[tid];
    __syncthreads();

    const int  preal  = blockIdx.x * PAIRS_ACTIVE + pid;
    const bool active = (pid < PAIRS_ACTIVE) && (preal < NPTS);
    const int  p  = active ? preal : (NPTS - 1);
    const int  b  = p / 200;
    const int  c  = p - b * 200;
    const float* xb = x + b * XROW;

    float y0 = xb[2 + 2 * c];
    float y1 = xb[3 + 2 * c];
    float ts = xb[0];
    const float sp0 = xb[402];
    const float tA0 = fmaf(xb[403], sm[OWT+0], xb[404] * sm[OWT+1]);
    const float tA1 = fmaf(xb[403], sm[OWT+2], xb[404] * sm[OWT+3]);
    const float tB0 = fmaf(xb[405], sm[OWT+0], xb[406] * sm[OWT+1]);
    const float tB1 = fmaf(xb[405], sm[OWT+2], xb[406] * sm[OWT+3]);

    const float* __restrict__ smv = sm;

    #define XCHG(arr, lo0, hi0, t, val)                                        \
        do {                                                                   \
            u64 _oth = __shfl_xor_sync(0xffffffffu, (val), 1);                 \
            u64 _lo_o, _hi_o, _lo_t, _hi_t;                                    \
            dup2((val), _lo_o, _hi_o);                                         \
            dup2(_oth, _lo_t, _hi_t);                                          \
            (arr)[(lo0) + 2*(t)]     = hb ? _lo_t : _lo_o;                     \
            (arr)[(lo0) + 2*(t) + 1] = hb ? _hi_t : _hi_o;                     \
            (arr)[(hi0) + 2*(t)]     = hb ? _lo_o : _lo_t;                     \
            (arr)[(hi0) + 2*(t) + 1] = hb ? _hi_o : _hi_t;                     \
        } while (0)

    #pragma unroll 1
    for (int it = 0; it < NSTEPS; ++it) {
        const bool  early = (ts < sp0);
        const float ti0 = early ? tA0 : tB0;
        const float ti1 = early ? tA1 : tB1;

        const u64 yd0 = pk(y0, y0), yd1 = pk(y1, y1);

        // ---- L1: own 4 neuron-pairs ----
        u64 h1p[4];
        #pragma unroll
        for (int t = 0; t < 4; ++t) {
            const float* rp = smv + OW0P + t*8 + half*4;
            u64 wa = *(const u64*)rp;
            u64 wb = *(const u64*)(rp + 2);
            u64 bb = *(const u64*)(smv + OB0s + 8*half + 2*t);
            h1p[t] = softplus2(ffma2(wa, yd0, ffma2(wb, yd1, bb)));
        }
        u64 vd16[16];
        #pragma unroll
        for (int t = 0; t < 4; ++t) XCHG(vd16, 0, 8, t, h1p[t]);

        // ---- L2: own 8 pairs; chunks at pairbase + c*32B + h*16B ----
        u64 h2p[8];
        #pragma unroll
        for (int t = 0; t < 8; ++t) {
            u64 z = *(const u64*)(smv + OB1s + 16*half + 2*t);
            const ulonglong2* wr = (const ulonglong2*)(smv + OF1 + t*64 + half*4);
            #pragma unroll
            for (int k = 0; k < 8; ++k) {
                ulonglong2 w = wr[2*k];
                z = ffma2(w.x, vd16[2*k], z);
                z = ffma2(w.y, vd16[2*k + 1], z);
            }
            h2p[t] = softplus2(z);
        }
        u64 vd32[32];
        #pragma unroll
        for (int t = 0; t < 8; ++t) XCHG(vd32, 0, 16, t, h2p[t]);

        // ---- L3: own 8 pairs ----
        u64 h3p[8];
        #pragma unroll
        for (int t = 0; t < 8; ++t) {
            u64 z = *(const u64*)(smv + OB2s + 16*half + 2*t);
            const ulonglong2* wr = (const ulonglong2*)(smv + OF2 + t*128 + half*4);
            #pragma unroll
            for (int k = 0; k < 16; ++k) {
                ulonglong2 w = wr[2*k];
                z = ffma2(w.x, vd32[2*k], z);
                z = ffma2(w.y, vd32[2*k + 1], z);
            }
            h3p[t] = softplus2(z);
        }
        #pragma unroll
        for (int t = 0; t < 8; ++t) XCHG(vd32, 0, 16, t, h3p[t]);

        // ---- L4: own 4 pairs; g4 = sig(z)*w4 ----
        u64 g4p[4];
        #pragma unroll
        for (int t = 0; t < 4; ++t) {
            u64 z = *(const u64*)(smv + OB3s + 8*half + 2*t);
            const ulonglong2* wr = (const ulonglong2*)(smv + OF3 + t*128 + half*4);
            #pragma unroll
            for (int k = 0; k < 16; ++k) {
                ulonglong2 w = wr[2*k];
                z = ffma2(w.x, vd32[2*k], z);
                z = ffma2(w.y, vd32[2*k + 1], z);
            }
            g4p[t] = fmul2(sig2(z), *(const u64*)(smv + OW4 + 8*half + 2*t));
        }
        u64 gd16[16];
        #pragma unroll
        for (int t = 0; t < 4; ++t) XCHG(gd16, 0, 8, t, g4p[t]);

        // ---- g3: own col-halves (stride-32 rows; +0/+64B same line) ----
        u64 a[8];
        #pragma unroll
        for (int t = 0; t < 8; ++t) a[t] = 0ULL;
        #pragma unroll
        for (int o = 0; o < 16; ++o) {
            const u64 go = gd16[o];
            const ulonglong2* wr = (const ulonglong2*)(smv + OB3 + o*32 + 16*half);
            #pragma unroll
            for (int t = 0; t < 4; ++t) {
                ulonglong2 w = wr[t];
                a[2*t]     = ffma2(w.x, go, a[2*t]);
                a[2*t + 1] = ffma2(w.y, go, a[2*t + 1]);
            }
        }
        #pragma unroll
        for (int t = 0; t < 8; ++t) {
            u64 g3 = fmul2(a[t], sig2h(h3p[t]));
            XCHG(vd32, 0, 16, t, g3);
        }

        // ---- g2 ----
        #pragma unroll
        for (int t = 0; t < 8; ++t) a[t] = 0ULL;
        #pragma unroll
        for (int o = 0; o < 32; ++o) {
            const u64 go = vd32[o];
            const ulonglong2* wr = (const ulonglong2*)(smv + OB2 + o*32 + 16*half);
            #pragma unroll
            for (int t = 0; t < 4; ++t) {
                ulonglong2 w = wr[t];
                a[2*t]     = ffma2(w.x, go, a[2*t]);
                a[2*t + 1] = ffma2(w.y, go, a[2*t + 1]);
            }
        }
        #pragma unroll
        for (int t = 0; t < 8; ++t) {
            u64 g2 = fmul2(a[t], sig2h(h2p[t]));
            XCHG(vd32, 0, 16, t, g2);
        }

        // ---- g1 + gy ----
        u64 a4[4];
        #pragma unroll
        for (int t = 0; t < 4; ++t) a4[t] = 0ULL;
        #pragma unroll
        for (int o = 0; o < 32; ++o) {
            const u64 go = vd32[o];
            const ulonglong2* wr = (const ulonglong2*)(smv + OB1 + o*16 + 8*half);
            #pragma unroll
            for (int t = 0; t < 2; ++t) {
                ulonglong2 w = wr[t];
                a4[2*t]     = ffma2(w.x, go, a4[2*t]);
                a4[2*t + 1] = ffma2(w.y, go, a4[2*t + 1]);
            }
        }
        u64 gy0p = 0ULL, gy1p = 0ULL;
        #pragma unroll
        for (int t = 0; t < 4; ++t) {
            u64 g1 = fmul2(a4[t], sig2h(h1p[t]));
            const float* rp = smv + OW0P + t*8 + half*4;
            gy0p = ffma2(*(const u64*)rp,       g1, gy0p);
            gy1p = ffma2(*(const u64*)(rp + 2), g1, gy1p);
        }
        float u, v;
        upk(gy0p, u, v); float gy0 = u + v;
        upk(gy1p, u, v); float gy1 = u + v;
        gy0 += __shfl_xor_sync(0xffffffffu, gy0, 1);
        gy1 += __shfl_xor_sync(0xffffffffu, gy1, 1);

        y0 = fmaf(-(gy0 + ti0), DTF, y0);
        y1 = fmaf(-(gy1 + ti1), DTF, y1);
        ts += DTF;
    }

    if (active) out[2 * p + half] = hb ? y1 : y0;
}

extern "C" void kernel_launch(void* const* d_in, const int* in_sizes, int n_in,
                              void* d_out, int out_size)
{
    int xi = -1;
    for (int i = 0; i < n_in; ++i)
        if (in_sizes[i] == 128 * XROW) { xi = i; break; }

    const float *x, *W[5], *B[5], *wtp;
    if (xi == 0) {
        x = (const float*)d_in[0];
        for (int i = 0; i < 5; ++i) {
            W[i] = (const float*)d_in[1 + 2 * i];
            B[i] = (const float*)d_in[2 + 2 * i];
        }
        wtp = (const float*)d_in[11];
    } else {
        for (int i = 0; i < 5; ++i) {
            W[i] = (const float*)d_in[2 * i];
            B[i] = (const float*)d_in[2 * i + 1];
        }
        wtp = (const float*)d_in[10];
        x   = (const float*)d_in[(xi >= 0) ? xi : 11];
    }

    float* out = (float*)d_out;
    phinn_kernel<<<NBLK, TPB>>>(x,
                                W[0], B[0], W[1], B[1], W[2], B[2],
                                W[3], B[3], W[4], wtp, out);
}